// round 2
// baseline (speedup 1.0000x reference)
#include <cuda_runtime.h>
#include <cstdint>

#define FULL 0xFFFFFFFFu

// Scratch: feat transposed [k=2048][b=32], k-major so GEMM loads are
// coalesced/broadcast-friendly. 256KB static device array (no allocation).
__device__ float g_featT[2048 * 32];

// Order-preserving float <-> uint mapping (total order matches float order
// for non-NaN values).
__device__ __forceinline__ unsigned f2ord(float f) {
    unsigned b = __float_as_uint(f);
    return (b & 0x80000000u) ? ~b : (b | 0x80000000u);
}
__device__ __forceinline__ float ord2f(unsigned u) {
    unsigned b = (u & 0x80000000u) ? (u ^ 0x80000000u) : ~u;
    return __uint_as_float(b);
}

// ---------------------------------------------------------------------------
// Kernel A: per-batch prep. grid = 32 (one block per batch), 256 threads.
//  - out[b,:] = bias + flag_b * token   (also un-poisons d_out)
//  - inv_r = 1/max(||f_rad[b]||, eps), inv_h likewise
//  - top-16 / bottom-16 sums of f_histo[b] (selection via REDUX.SYNC passes)
//  - featT[k][b] for k in [0,2048)
// ---------------------------------------------------------------------------
__global__ void __launch_bounds__(256) prep_kernel(
    const float* __restrict__ f_rad,    // [32,1024]
    const float* __restrict__ f_histo,  // [32,2048]
    const int*   __restrict__ rad_mask, // [32]
    const int*   __restrict__ histo_mask,
    const float* __restrict__ bias,     // [1024]
    const float* __restrict__ token,    // [1024]
    float* __restrict__ out)            // [32,1024]
{
    const int b    = blockIdx.x;
    const int tid  = threadIdx.x;
    const int lane = tid & 31;
    const int wid  = tid >> 5;

    __shared__ float    s_red[16];   // 8 warp partials rad + 8 histo
    __shared__ unsigned s_candT[64];
    __shared__ unsigned s_candB[64];
    __shared__ float    s_scal[4];   // inv_r, inv_h, sum_top, sum_bot

    // --- out init: bias + token*flag (token is all-zero per setup, but be general)
    float flag = ((rad_mask[b] != 0) && (histo_mask[b] != 0)) ? 0.f : 1.f;
    for (int c = tid; c < 1024; c += 256)
        out[b * 1024 + c] = bias[c] + flag * token[c];

    const float* rad = f_rad   + b * 1024;
    const float* his = f_histo + b * 2048;

    // --- norms (sum of squares), warp shuffle + smem reduce
    float sr = 0.f, sh = 0.f;
    #pragma unroll
    for (int j = 0; j < 4; j++) { float v = rad[tid + 256 * j]; sr += v * v; }
    #pragma unroll
    for (int j = 0; j < 8; j++) { float v = his[tid + 256 * j]; sh += v * v; }
    #pragma unroll
    for (int o = 16; o > 0; o >>= 1) {
        sr += __shfl_xor_sync(FULL, sr, o);
        sh += __shfl_xor_sync(FULL, sh, o);
    }
    if (lane == 0) { s_red[wid] = sr; s_red[8 + wid] = sh; }
    __syncthreads();
    if (tid == 0) {
        float a = 0.f, c2 = 0.f;
        #pragma unroll
        for (int w = 0; w < 8; w++) { a += s_red[w]; c2 += s_red[8 + w]; }
        s_scal[0] = 1.f / fmaxf(sqrtf(a),  1e-12f);
        s_scal[1] = 1.f / fmaxf(sqrtf(c2), 1e-12f);
    }

    // --- selection: warps 0-3 find local top-16 over 512 elems each,
    //     warps 4-7 find local bottom-16. Values live in 16 registers/lane.
    unsigned v[16];
    {
        const int base = (wid & 3) * 512;
        #pragma unroll
        for (int j = 0; j < 16; j++)
            v[j] = f2ord(his[base + j * 32 + lane]);
    }

    if (wid < 4) {
        #pragma unroll 1
        for (int p = 0; p < 16; p++) {
            unsigned lm = 0u;
            #pragma unroll
            for (int j = 0; j < 16; j++) lm = max(lm, v[j]);
            unsigned wm   = __reduce_max_sync(FULL, lm);   // REDUX.SYNC
            unsigned ball = __ballot_sync(FULL, lm == wm);
            if (lane == __ffs(ball) - 1) {                 // one lane removes one instance
                bool d = false;
                #pragma unroll
                for (int j = 0; j < 16; j++)
                    if (!d && v[j] == wm) { v[j] = 0u; d = true; }
            }
            if (lane == 0) s_candT[(wid & 3) * 16 + p] = wm;
        }
    } else {
        #pragma unroll 1
        for (int p = 0; p < 16; p++) {
            unsigned lm = 0xFFFFFFFFu;
            #pragma unroll
            for (int j = 0; j < 16; j++) lm = min(lm, v[j]);
            unsigned wm   = __reduce_min_sync(FULL, lm);
            unsigned ball = __ballot_sync(FULL, lm == wm);
            if (lane == __ffs(ball) - 1) {
                bool d = false;
                #pragma unroll
                for (int j = 0; j < 16; j++)
                    if (!d && v[j] == wm) { v[j] = 0xFFFFFFFFu; d = true; }
            }
            if (lane == 0) s_candB[(wid - 4) * 16 + p] = wm;
        }
    }
    __syncthreads();

    // --- merge 4x16 candidates -> global top-16 sum (warp 0), bottom (warp 1)
    if (wid == 0) {
        unsigned a0 = s_candT[lane], a1 = s_candT[32 + lane];
        float ssum = 0.f;
        #pragma unroll 1
        for (int p = 0; p < 16; p++) {
            unsigned lm = max(a0, a1);
            unsigned wm = __reduce_max_sync(FULL, lm);
            ssum += ord2f(wm);
            unsigned ball = __ballot_sync(FULL, lm == wm);
            if (lane == __ffs(ball) - 1) {
                if (a0 == wm) a0 = 0u; else a1 = 0u;
            }
        }
        if (lane == 0) s_scal[2] = ssum;
    } else if (wid == 1) {
        unsigned a0 = s_candB[lane], a1 = s_candB[32 + lane];
        float ssum = 0.f;
        #pragma unroll 1
        for (int p = 0; p < 16; p++) {
            unsigned lm = min(a0, a1);
            unsigned wm = __reduce_min_sync(FULL, lm);
            ssum += ord2f(wm);
            unsigned ball = __ballot_sync(FULL, lm == wm);
            if (lane == __ffs(ball) - 1) {
                if (a0 == wm) a0 = 0xFFFFFFFFu; else a1 = 0xFFFFFFFFu;
            }
        }
        if (lane == 0) s_scal[3] = ssum;
    }
    __syncthreads();

    const float inv_r = s_scal[0];
    const float inv_h = s_scal[1];
    const float Tp = inv_h * s_scal[2] * (1.f / 16.f);  // mean of top-16 of normalized h
    const float Tn = inv_h * s_scal[3] * (1.f / 16.f);  // mean of bottom-16

    // featT:
    //   pos(k)      = Tp*max(r,0) + Tn*min(r,0)
    //   neg(k+1024) = -(Tn*max(r,0) + Tp*min(r,0))
    for (int i = tid; i < 1024; i += 256) {
        float r = rad[i] * inv_r;
        float p = fmaxf(r, 0.f), m = fminf(r, 0.f);
        g_featT[i * 32 + b]          =  Tp * p + Tn * m;
        g_featT[(1024 + i) * 32 + b] = -(Tn * p + Tp * m);
    }
}

// ---------------------------------------------------------------------------
// Kernel B: skinny GEMM  out[b,c] += sum_k featT[k][b] * W[c,k]
// grid = (8 c-tiles of 128, 32 k-splits of 64), 256 threads.
// smem-staged W (k-major, pad 132) + featT chunk; 4c x 4b register micro-tile.
// Split-K partials accumulated with atomicAdd (out pre-initialized by prep).
// ---------------------------------------------------------------------------
__global__ void __launch_bounds__(256) gemm_kernel(
    const float* __restrict__ W,   // [1024, 2048] row-major
    float* __restrict__ out)       // [32, 1024]
{
    const int c0  = blockIdx.x * 128;
    const int k0  = blockIdx.y * 64;
    const int tid = threadIdx.x;

    __shared__ float Ws[64 * 132];  // [k][c], pad 132 -> conflict-free LDS.128
    __shared__ float Fs[64 * 32];   // [k][b]

    // Stage W tile: 128 c-rows x 64 k. Coalesced LDG.128 along k.
    const float4* W4 = (const float4*)W;
    const int kq0 = k0 >> 2;
    for (int i = tid; i < 2048; i += 256) {
        int kblk = i & 15;   // which float4 along k (0..15)
        int cl   = i >> 4;   // c within tile (0..127)
        float4 vv = W4[(size_t)(c0 + cl) * 512 + kq0 + kblk];
        int kk = kblk * 4;
        Ws[(kk + 0) * 132 + cl] = vv.x;
        Ws[(kk + 1) * 132 + cl] = vv.y;
        Ws[(kk + 2) * 132 + cl] = vv.z;
        Ws[(kk + 3) * 132 + cl] = vv.w;
    }
    for (int i = tid; i < 2048; i += 256)
        Fs[i] = g_featT[k0 * 32 + i];
    __syncthreads();

    const int cg = tid & 31;   // c group: c = c0 + cg*4 .. +3
    const int bg = tid >> 5;   // b group: b = bg*4 .. +3 (whole warp shares bg)

    float acc[4][4] = {};
    #pragma unroll 4
    for (int k = 0; k < 64; k++) {
        float4 wv = *(const float4*)&Ws[k * 132 + cg * 4];  // conflict-free
        float4 fv = *(const float4*)&Fs[k * 32  + bg * 4];  // warp broadcast
        float wr[4] = { wv.x, wv.y, wv.z, wv.w };
        float fr[4] = { fv.x, fv.y, fv.z, fv.w };
        #pragma unroll
        for (int i = 0; i < 4; i++)
            #pragma unroll
            for (int j = 0; j < 4; j++)
                acc[i][j] = fmaf(wr[i], fr[j], acc[i][j]);
    }

    #pragma unroll
    for (int j = 0; j < 4; j++) {
        int b = bg * 4 + j;
        #pragma unroll
        for (int i = 0; i < 4; i++)
            atomicAdd(&out[b * 1024 + c0 + cg * 4 + i], acc[i][j]);
    }
}

extern "C" void kernel_launch(void* const* d_in, const int* in_sizes, int n_in,
                              void* d_out, int out_size) {
    const float* f_rad      = (const float*)d_in[0];
    const float* f_histo    = (const float*)d_in[1];
    const int*   rad_mask   = (const int*)  d_in[2];
    const int*   histo_mask = (const int*)  d_in[3];
    const float* W          = (const float*)d_in[4];
    const float* bias       = (const float*)d_in[5];
    const float* token      = (const float*)d_in[6];
    float* out = (float*)d_out;

    prep_kernel<<<32, 256>>>(f_rad, f_histo, rad_mask, histo_mask, bias, token, out);
    gemm_kernel<<<dim3(8, 32), 256>>>(W, out);
}